// round 1
// baseline (speedup 1.0000x reference)
#include <cuda_runtime.h>
#include <cstdint>

#define NB    2
#define NPTS  16384
#define MC3   8192
#define NROI  128
#define NKP   2048
#define CBEV  256
#define CRAW  32
#define CC3   64
#define CF    (CBEV + CRAW + CC3)   // 352
#define COUT  128
#define HW    188

// ---------------- scratch (device globals; no allocation allowed) -----------
__device__ float g_px[NB][NPTS], g_py[NB][NPTS], g_pz[NB][NPTS];
__device__ unsigned char g_valid[NB][NPTS];
__device__ float g_cx[NB][MC3], g_cy[NB][MC3], g_cz[NB][MC3];
__device__ float g_kpx[NB][NKP], g_kpy[NB][NKP], g_kpz[NB][NKP];
__device__ float g_fraw[NB * NPTS * CRAW];   // relu(pfeat @ W_raw + b)
__device__ float g_fc3[NB * MC3 * CC3];      // relu(cfeat @ W_c3 + b)
__device__ float g_feats[NB * NKP * CF];     // [bev | raw_agg | c3_agg]

// ---------------- 1) SoA copy of point xyz + ROI validity -------------------
__global__ void prep_points_kernel(const float* __restrict__ points,
                                   const float* __restrict__ bboxes) {
    int tid = blockIdx.x * blockDim.x + threadIdx.x;
    if (tid >= NB * NPTS) return;
    int b = tid / NPTS, i = tid % NPTS;
    const float* p = points + (size_t)tid * 5;
    float x = p[0], y = p[1], z = p[2];
    g_px[b][i] = x; g_py[b][i] = y; g_pz[b][i] = z;

    // argmin over sqrt distances (strict <  ==> first-index tie-break, matching jnp.argmin)
    float best = 3.0e38f;
    int bidx = 0;
    const float* bb0 = bboxes + (size_t)b * NROI * 7;
    for (int r = 0; r < NROI; ++r) {
        const float* bb = bb0 + r * 7;
        float dx = x - bb[0], dy = y - bb[1], dz = z - bb[2];
        float d = __fsqrt_rn(dx * dx + dy * dy + dz * dz);
        if (d < best) { best = d; bidx = r; }
    }
    const float* bb = bb0 + bidx * 7;
    float hx = bb[3] * 0.5f, hy = bb[4] * 0.5f, hz = bb[5] * 0.5f;
    float rm = __fsqrt_rn(hx * hx + hy * hy + hz * hz);
    g_valid[b][i] = (best < rm + 2.4f) ? 1 : 0;
}

__global__ void prep_c3_kernel(const float* __restrict__ conv3) {
    int tid = blockIdx.x * blockDim.x + threadIdx.x;
    if (tid >= NB * MC3) return;
    int b = tid / MC3, i = tid % MC3;
    const float* p = conv3 + (size_t)tid * 67;
    g_cx[b][i] = p[0]; g_cy[b][i] = p[1]; g_cz[b][i] = p[2];
}

// ---------------- 2) per-point MLPs -----------------------------------------
__global__ void fraw_kernel(const float* __restrict__ points,
                            const float* __restrict__ W,   // (2,32)
                            const float* __restrict__ bias) {
    int tid = blockIdx.x * blockDim.x + threadIdx.x;
    if (tid >= NB * NPTS * CRAW) return;
    int c = tid & (CRAW - 1);
    int pi = tid >> 5;
    const float* p = points + (size_t)pi * 5;
    float v = p[3] * W[c] + p[4] * W[CRAW + c] + bias[c];
    g_fraw[tid] = fmaxf(v, 0.0f);
}

__global__ void fc3_kernel(const float* __restrict__ conv3,
                           const float* __restrict__ W,    // (64,64)
                           const float* __restrict__ bias) {
    int tid = blockIdx.x * blockDim.x + threadIdx.x;
    if (tid >= NB * MC3 * CC3) return;
    int c = tid & (CC3 - 1);
    int pi = tid >> 6;
    const float* p = conv3 + (size_t)pi * 67 + 3;
    float acc = 0.0f;
    #pragma unroll 8
    for (int k = 0; k < CC3; ++k) acc += p[k] * W[k * CC3 + c];
    g_fc3[tid] = fmaxf(acc + bias[c], 0.0f);
}

// ---------------- 3) farthest point sampling (sequential core) --------------
// One 1024-thread block per batch. d[16] lives in registers; xyz streamed from
// SoA arrays (L1-resident). Argmax: warp shuffle + 32-slot smem + warp0 reduce.
// Tie-break: lowest global index (matches jnp.argmax).
__global__ void __launch_bounds__(1024, 1) fps_kernel() {
    int b = blockIdx.x;
    int t = threadIdx.x;
    int lane = t & 31, warp = t >> 5;
    const float* px = g_px[b];
    const float* py = g_py[b];
    const float* pz = g_pz[b];

    float dd[16];
    #pragma unroll
    for (int j = 0; j < 16; ++j) {
        int i = j * 1024 + t;
        dd[j] = g_valid[b][i] ? 1.0e10f : -1.0e10f;
    }

    __shared__ float s_bv[32];
    __shared__ int   s_bi[32];
    __shared__ int   s_sel;

    for (int it = 0; it < NKP; ++it) {
        // local argmax over the 16 owned entries
        float bv = dd[0];
        int   bi = t;
        #pragma unroll
        for (int j = 1; j < 16; ++j) {
            float v = dd[j];
            if (v > bv) { bv = v; bi = j * 1024 + t; }
        }
        // warp reduce (max value, min index on ties)
        #pragma unroll
        for (int o = 16; o > 0; o >>= 1) {
            float ov = __shfl_down_sync(0xffffffffu, bv, o);
            int   oi = __shfl_down_sync(0xffffffffu, bi, o);
            if (ov > bv || (ov == bv && oi < bi)) { bv = ov; bi = oi; }
        }
        if (lane == 0) { s_bv[warp] = bv; s_bi[warp] = bi; }
        __syncthreads();
        if (warp == 0) {
            bv = s_bv[lane];
            bi = s_bi[lane];
            #pragma unroll
            for (int o = 16; o > 0; o >>= 1) {
                float ov = __shfl_down_sync(0xffffffffu, bv, o);
                int   oi = __shfl_down_sync(0xffffffffu, bi, o);
                if (ov > bv || (ov == bv && oi < bi)) { bv = ov; bi = oi; }
            }
            if (lane == 0) s_sel = bi;
        }
        __syncthreads();
        int sel = s_sel;
        float kx = px[sel], ky = py[sel], kz = pz[sel];   // broadcast loads
        if (t == 0) { g_kpx[b][it] = kx; g_kpy[b][it] = ky; g_kpz[b][it] = kz; }
        // min-distance update (invalid entries stay -1e10; fmin is safe)
        #pragma unroll
        for (int j = 0; j < 16; ++j) {
            int i = j * 1024 + t;
            float dx = px[i] - kx, dy = py[i] - ky, dz = pz[i] - kz;
            float nd = dx * dx + dy * dy + dz * dz;
            dd[j] = fminf(dd[j], nd);
        }
    }
}

// ---------------- 4) bilinear BEV sampling ----------------------------------
__global__ void bev_kernel(const float* __restrict__ sf) {
    int k = blockIdx.x, b = blockIdx.y, c = threadIdx.x;   // c in [0,256)
    float kx = g_kpx[b][k], ky = g_kpy[b][k];
    float xi = __fdiv_rn(__fdiv_rn(kx - (-75.2f), 0.1f), 8.0f);
    float yi = __fdiv_rn(__fdiv_rn(ky - (-75.2f), 0.1f), 8.0f);
    int x0 = min(max((int)floorf(xi), 0), HW - 1);
    int x1 = min(x0 + 1, HW - 1);
    int y0 = min(max((int)floorf(yi), 0), HW - 1);
    int y1 = min(y0 + 1, HW - 1);
    float xf0 = (float)x0, xf1 = (float)x1, yf0 = (float)y0, yf1 = (float)y1;
    float wa = (xf1 - xi) * (yf1 - yi);
    float wb = (xf1 - xi) * (yi - yf0);
    float wc = (xi - xf0) * (yf1 - yi);
    float wd = (xi - xf0) * (yi - yf0);
    const float* im = sf + ((size_t)b * CBEV + c) * (HW * HW);
    float Ia = im[y0 * HW + x0];
    float Ib = im[y1 * HW + x0];
    float Ic = im[y0 * HW + x1];
    float Id = im[y1 * HW + x1];
    g_feats[((size_t)b * NKP + k) * CF + c] = Ia * wa + Ib * wb + Ic * wc + Id * wd;
}

// ---------------- 5) radius aggregation (ballot-broadcast) ------------------
// 8 warps/block, 1 keypoint/warp, 256-point smem tiles. Hits are rare
// (expected ~0.3 / ~1.0 neighbors per keypoint) so the serialized broadcast
// accumulation is essentially free.
__global__ void agg_raw_kernel(float r2) {
    int b = blockIdx.y;
    int warp = threadIdx.x >> 5, lane = threadIdx.x & 31;
    int k = blockIdx.x * 8 + warp;
    float kx = g_kpx[b][k], ky = g_kpy[b][k], kz = g_kpz[b][k];
    float acc = 0.0f;
    int cnt = 0;
    __shared__ float sx[256], sy[256], sz[256];
    for (int base = 0; base < NPTS; base += 256) {
        __syncthreads();
        int i = base + threadIdx.x;
        sx[threadIdx.x] = g_px[b][i];
        sy[threadIdx.x] = g_py[b][i];
        sz[threadIdx.x] = g_pz[b][i];
        __syncthreads();
        #pragma unroll
        for (int s = 0; s < 8; ++s) {
            int j = s * 32 + lane;
            float dx = sx[j] - kx, dy = sy[j] - ky, dz = sz[j] - kz;
            float d2 = dx * dx + dy * dy + dz * dz;
            unsigned m = __ballot_sync(0xffffffffu, d2 < r2);
            while (m) {
                int src = __ffs(m) - 1;
                m &= m - 1;
                int gp = base + s * 32 + src;
                acc += g_fraw[((size_t)b * NPTS + gp) * CRAW + lane];
                cnt++;
            }
        }
    }
    float c = fmaxf((float)cnt, 1.0f);
    g_feats[((size_t)b * NKP + k) * CF + CBEV + lane] = acc / c;
}

__global__ void agg_c3_kernel(float r2) {
    int b = blockIdx.y;
    int warp = threadIdx.x >> 5, lane = threadIdx.x & 31;
    int k = blockIdx.x * 8 + warp;
    float kx = g_kpx[b][k], ky = g_kpy[b][k], kz = g_kpz[b][k];
    float acc0 = 0.0f, acc1 = 0.0f;
    int cnt = 0;
    __shared__ float sx[256], sy[256], sz[256];
    for (int base = 0; base < MC3; base += 256) {
        __syncthreads();
        int i = base + threadIdx.x;
        sx[threadIdx.x] = g_cx[b][i];
        sy[threadIdx.x] = g_cy[b][i];
        sz[threadIdx.x] = g_cz[b][i];
        __syncthreads();
        #pragma unroll
        for (int s = 0; s < 8; ++s) {
            int j = s * 32 + lane;
            float dx = sx[j] - kx, dy = sy[j] - ky, dz = sz[j] - kz;
            float d2 = dx * dx + dy * dy + dz * dz;
            unsigned m = __ballot_sync(0xffffffffu, d2 < r2);
            while (m) {
                int src = __ffs(m) - 1;
                m &= m - 1;
                int gp = base + s * 32 + src;
                const float* fp = g_fc3 + ((size_t)b * MC3 + gp) * CC3;
                acc0 += fp[lane];
                acc1 += fp[lane + 32];
                cnt++;
            }
        }
    }
    float c = fmaxf((float)cnt, 1.0f);
    float* o = g_feats + ((size_t)b * NKP + k) * CF + CBEV + CRAW;
    o[lane] = acc0 / c;
    o[lane + 32] = acc1 / c;
}

// ---------------- 6) fuse GEMM + BN + ReLU ----------------------------------
#define ROWS_PB 16
__global__ void fuse_kernel(const float* __restrict__ W,       // (352,128)
                            const float* __restrict__ gamma,
                            const float* __restrict__ beta,
                            const float* __restrict__ mean,
                            const float* __restrict__ var,
                            float* __restrict__ out) {
    __shared__ float sf[ROWS_PB][CF];
    int row0 = blockIdx.x * ROWS_PB;
    int tid = threadIdx.x;   // 128 threads
    for (int idx = tid; idx < ROWS_PB * CF; idx += 128) {
        ((float*)sf)[idx] = g_feats[(size_t)row0 * CF + idx];
    }
    __syncthreads();
    int c = tid;
    float acc[ROWS_PB];
    #pragma unroll
    for (int r = 0; r < ROWS_PB; ++r) acc[r] = 0.0f;
    for (int k = 0; k < CF; ++k) {
        float w = W[k * COUT + c];
        #pragma unroll
        for (int r = 0; r < ROWS_PB; ++r) acc[r] += sf[r][k] * w;
    }
    float mu = mean[c];
    float iv = rsqrtf(var[c] + 1e-5f);
    float g = gamma[c], be = beta[c];
    #pragma unroll
    for (int r = 0; r < ROWS_PB; ++r) {
        float v = (acc[r] - mu) * iv * g + be;
        out[(size_t)(row0 + r) * COUT + c] = fmaxf(v, 0.0f);
    }
}

// ---------------- 7) keypoints output ---------------------------------------
__global__ void kpout_kernel(float* __restrict__ out) {
    int tid = blockIdx.x * blockDim.x + threadIdx.x;
    if (tid >= NB * NKP * 3) return;
    int b = tid / (NKP * 3);
    int rem = tid % (NKP * 3);
    int k = rem / 3, d = rem % 3;
    float v = (d == 0) ? g_kpx[b][k] : (d == 1 ? g_kpy[b][k] : g_kpz[b][k]);
    out[(size_t)NB * NKP * COUT + tid] = v;
}

// ---------------- launcher ---------------------------------------------------
extern "C" void kernel_launch(void* const* d_in, const int* in_sizes, int n_in,
                              void* d_out, int out_size) {
    const float* points  = (const float*)d_in[0];   // (2,16384,5)
    const float* bboxes  = (const float*)d_in[1];   // (2,128,7)
    const float* spatial = (const float*)d_in[2];   // (2,256,188,188)
    const float* conv3   = (const float*)d_in[3];   // (2,8192,67)
    const float* W_raw   = (const float*)d_in[4];
    const float* b_raw   = (const float*)d_in[5];
    const float* W_c3    = (const float*)d_in[6];
    const float* b_c3    = (const float*)d_in[7];
    const float* W_fuse  = (const float*)d_in[8];
    const float* bn_g    = (const float*)d_in[9];
    const float* bn_b    = (const float*)d_in[10];
    const float* bn_m    = (const float*)d_in[11];
    const float* bn_v    = (const float*)d_in[12];
    float* out = (float*)d_out;

    prep_points_kernel<<<(NB * NPTS + 255) / 256, 256>>>(points, bboxes);
    prep_c3_kernel<<<(NB * MC3 + 255) / 256, 256>>>(conv3);
    fraw_kernel<<<(NB * NPTS * CRAW + 255) / 256, 256>>>(points, W_raw, b_raw);
    fc3_kernel<<<(NB * MC3 * CC3 + 255) / 256, 256>>>(conv3, W_c3, b_c3);
    fps_kernel<<<NB, 1024>>>();
    bev_kernel<<<dim3(NKP, NB), CBEV>>>(spatial);
    agg_raw_kernel<<<dim3(NKP / 8, NB), 256>>>(0.8f * 0.8f);
    agg_c3_kernel<<<dim3(NKP / 8, NB), 256>>>(1.6f * 1.6f);
    fuse_kernel<<<(NB * NKP) / ROWS_PB, COUT>>>(W_fuse, bn_g, bn_b, bn_m, bn_v, out);
    kpout_kernel<<<(NB * NKP * 3 + 255) / 256, 256>>>(out);
}

// round 2
// speedup vs baseline: 1.9828x; 1.9828x over previous
#include <cuda_runtime.h>
#include <cstdint>

#define NB    2
#define NPTS  16384
#define MC3   8192
#define NROI  128
#define NKP   2048
#define CBEV  256
#define CRAW  32
#define CC3   64
#define CF    (CBEV + CRAW + CC3)   // 352
#define COUT  128
#define HW    188

typedef unsigned long long ull;

// ---------------- f32x2 packed helpers (sm_103a) ----------------------------
__device__ __forceinline__ ull f2pack(float lo, float hi) {
    ull r; asm("mov.b64 %0,{%1,%2};" : "=l"(r) : "f"(lo), "f"(hi)); return r;
}
__device__ __forceinline__ void f2unpack(ull v, float& lo, float& hi) {
    asm("mov.b64 {%0,%1},%2;" : "=f"(lo), "=f"(hi) : "l"(v));
}
__device__ __forceinline__ ull f2add(ull a, ull b) {
    ull r; asm("add.rn.f32x2 %0,%1,%2;" : "=l"(r) : "l"(a), "l"(b)); return r;
}
__device__ __forceinline__ ull f2mul(ull a, ull b) {
    ull r; asm("mul.rn.f32x2 %0,%1,%2;" : "=l"(r) : "l"(a), "l"(b)); return r;
}
__device__ __forceinline__ ull f2fma(ull a, ull b, ull c) {
    ull r; asm("fma.rn.f32x2 %0,%1,%2,%3;" : "=l"(r) : "l"(a), "l"(b), "l"(c)); return r;
}

// monotonic float <-> uint key (total order, max-compatible)
__device__ __forceinline__ unsigned fkey(float f) {
    unsigned b = __float_as_uint(f);
    return b ^ ((unsigned)((int)b >> 31) | 0x80000000u);
}
__device__ __forceinline__ float keyf(unsigned k) {
    unsigned b = (k & 0x80000000u) ? (k ^ 0x80000000u) : ~k;
    return __uint_as_float(b);
}

// ---------------- scratch (device globals; no allocation allowed) -----------
__device__ float g_px[NB][NPTS], g_py[NB][NPTS], g_pz[NB][NPTS];
__device__ unsigned char g_valid[NB][NPTS];
__device__ float g_cx[NB][MC3], g_cy[NB][MC3], g_cz[NB][MC3];
__device__ float g_kpx[NB][NKP], g_kpy[NB][NKP], g_kpz[NB][NKP];
__device__ float g_fraw[NB * NPTS * CRAW];
__device__ float g_fc3[NB * MC3 * CC3];
__device__ float g_feats[NB * NKP * CF];

// ---------------- 1) SoA copy of point xyz + ROI validity -------------------
__global__ void prep_points_kernel(const float* __restrict__ points,
                                   const float* __restrict__ bboxes) {
    int tid = blockIdx.x * blockDim.x + threadIdx.x;
    if (tid >= NB * NPTS) return;
    int b = tid / NPTS, i = tid % NPTS;
    const float* p = points + (size_t)tid * 5;
    float x = p[0], y = p[1], z = p[2];
    g_px[b][i] = x; g_py[b][i] = y; g_pz[b][i] = z;

    float best = 3.0e38f;
    int bidx = 0;
    const float* bb0 = bboxes + (size_t)b * NROI * 7;
    for (int r = 0; r < NROI; ++r) {
        const float* bb = bb0 + r * 7;
        float dx = x - bb[0], dy = y - bb[1], dz = z - bb[2];
        float d = __fsqrt_rn(dx * dx + dy * dy + dz * dz);
        if (d < best) { best = d; bidx = r; }
    }
    const float* bb = bb0 + bidx * 7;
    float hx = bb[3] * 0.5f, hy = bb[4] * 0.5f, hz = bb[5] * 0.5f;
    float rm = __fsqrt_rn(hx * hx + hy * hy + hz * hz);
    g_valid[b][i] = (best < rm + 2.4f) ? 1 : 0;
}

__global__ void prep_c3_kernel(const float* __restrict__ conv3) {
    int tid = blockIdx.x * blockDim.x + threadIdx.x;
    if (tid >= NB * MC3) return;
    int b = tid / MC3, i = tid % MC3;
    const float* p = conv3 + (size_t)tid * 67;
    g_cx[b][i] = p[0]; g_cy[b][i] = p[1]; g_cz[b][i] = p[2];
}

// ---------------- 2) per-point MLPs -----------------------------------------
__global__ void fraw_kernel(const float* __restrict__ points,
                            const float* __restrict__ W,
                            const float* __restrict__ bias) {
    int tid = blockIdx.x * blockDim.x + threadIdx.x;
    if (tid >= NB * NPTS * CRAW) return;
    int c = tid & (CRAW - 1);
    int pi = tid >> 5;
    const float* p = points + (size_t)pi * 5;
    float v = p[3] * W[c] + p[4] * W[CRAW + c] + bias[c];
    g_fraw[tid] = fmaxf(v, 0.0f);
}

__global__ void fc3_kernel(const float* __restrict__ conv3,
                           const float* __restrict__ W,
                           const float* __restrict__ bias) {
    int tid = blockIdx.x * blockDim.x + threadIdx.x;
    if (tid >= NB * MC3 * CC3) return;
    int c = tid & (CC3 - 1);
    int pi = tid >> 6;
    const float* p = conv3 + (size_t)pi * 67 + 3;
    float acc = 0.0f;
    #pragma unroll 8
    for (int k = 0; k < CC3; ++k) acc += p[k] * W[k * CC3 + c];
    g_fc3[tid] = fmaxf(acc + bias[c], 0.0f);
}

// ---------------- 3) farthest point sampling --------------------------------
// One 512-thread block per batch. Each thread owns 32 points (16 f32x2 pairs):
// x,y packed in registers, z + full xyz lookup copy in shared memory, dd in
// registers. Per-iteration: packed distance update (3 add + mul + 2 fma per
// pair on fma pipe), value-only max tracking (FMNMX), REDUX-based block max,
// rare predicated rescan + smem atomicMin for the argmax index (first-index
// tie-break == jnp.argmax).
__global__ void __launch_bounds__(512, 1) fps_kernel() {
    extern __shared__ float2 s_xyz[];          // xs[8192] ys[8192] zs[8192] = 192KB
    float2* xs = s_xyz;
    float2* ys = s_xyz + 8192;
    float2* zs = s_xyz + 16384;
    __shared__ unsigned s_wmax[16];
    __shared__ unsigned s_V;
    __shared__ int s_sel;

    int b = blockIdx.x;
    int t = threadIdx.x;
    int lane = t & 31, warp = t >> 5;

    const float2* px2 = (const float2*)g_px[b];
    const float2* py2 = (const float2*)g_py[b];
    const float2* pz2 = (const float2*)g_pz[b];
    const unsigned char* vv = g_valid[b];

    ull xp[16], yp[16];
    float dd[32];
    float bv = -1.0e10f;

    #pragma unroll
    for (int pp = 0; pp < 16; ++pp) {
        int gp = pp * 512 + t;
        float2 xv = px2[gp]; xs[gp] = xv; xp[pp] = f2pack(xv.x, xv.y);
        float2 yv = py2[gp]; ys[gp] = yv; yp[pp] = f2pack(yv.x, yv.y);
        zs[gp] = pz2[gp];
        float d0 = vv[2 * gp]     ? 1.0e10f : -1.0e10f;
        float d1 = vv[2 * gp + 1] ? 1.0e10f : -1.0e10f;
        dd[2 * pp] = d0; dd[2 * pp + 1] = d1;
        bv = fmaxf(bv, fmaxf(d0, d1));
    }
    if (t == 0) s_sel = 0x7fffffff;
    __syncthreads();

    for (int it = 0; it < NKP; ++it) {
        // ---- block max of dd (value only) ----
        unsigned key = fkey(bv);
        key = __reduce_max_sync(0xffffffffu, key);
        if (lane == 0) s_wmax[warp] = key;
        __syncthreads();                          // bar1
        if (warp == 0) {
            unsigned k2 = s_wmax[lane & 15];
            k2 = __reduce_max_sync(0xffffffffu, k2);
            if (lane == 0) s_V = k2;
        }
        if (t == 33) s_sel = 0x7fffffff;          // reset between bar1 and bar2
        __syncthreads();                          // bar2
        float V = keyf(s_V);

        // ---- index recovery (rare path; first-index tie-break) ----
        if (bv == V) {
            int cand = 0x7fffffff;
            #pragma unroll
            for (int j = 31; j >= 0; --j)
                if (dd[j] == V) cand = 1024 * (j >> 1) + 2 * t + (j & 1);
            atomicMin(&s_sel, cand);
        }
        __syncthreads();                          // bar3
        int sel = s_sel;
        float kx = ((const float*)xs)[sel];
        float ky = ((const float*)ys)[sel];
        float kz = ((const float*)zs)[sel];
        if (t == 0) { g_kpx[b][it] = kx; g_kpy[b][it] = ky; g_kpz[b][it] = kz; }
        if (it == NKP - 1) break;

        // ---- packed min-distance update + running max ----
        ull knx = f2pack(-kx, -kx);
        ull kny = f2pack(-ky, -ky);
        ull knz = f2pack(-kz, -kz);
        float bv0 = -1.0e10f, bv1 = -1.0e10f;
        #pragma unroll
        for (int pp = 0; pp < 16; ++pp) {
            ull dx = f2add(xp[pp], knx);
            ull dy = f2add(yp[pp], kny);
            float2 zv = zs[pp * 512 + t];
            ull dz = f2add(f2pack(zv.x, zv.y), knz);
            ull d2 = f2mul(dx, dx);
            d2 = f2fma(dy, dy, d2);
            d2 = f2fma(dz, dz, d2);
            float n0, n1; f2unpack(d2, n0, n1);
            float v0 = fminf(dd[2 * pp], n0);
            float v1 = fminf(dd[2 * pp + 1], n1);
            dd[2 * pp] = v0; dd[2 * pp + 1] = v1;
            bv0 = fmaxf(bv0, v0);
            bv1 = fmaxf(bv1, v1);
        }
        bv = fmaxf(bv0, bv1);
    }
}

// ---------------- 4) bilinear BEV sampling ----------------------------------
__global__ void bev_kernel(const float* __restrict__ sf) {
    int k = blockIdx.x, b = blockIdx.y, c = threadIdx.x;
    float kx = g_kpx[b][k], ky = g_kpy[b][k];
    float xi = __fdiv_rn(__fdiv_rn(kx - (-75.2f), 0.1f), 8.0f);
    float yi = __fdiv_rn(__fdiv_rn(ky - (-75.2f), 0.1f), 8.0f);
    int x0 = min(max((int)floorf(xi), 0), HW - 1);
    int x1 = min(x0 + 1, HW - 1);
    int y0 = min(max((int)floorf(yi), 0), HW - 1);
    int y1 = min(y0 + 1, HW - 1);
    float xf0 = (float)x0, xf1 = (float)x1, yf0 = (float)y0, yf1 = (float)y1;
    float wa = (xf1 - xi) * (yf1 - yi);
    float wb = (xf1 - xi) * (yi - yf0);
    float wc = (xi - xf0) * (yf1 - yi);
    float wd = (xi - xf0) * (yi - yf0);
    const float* im = sf + ((size_t)b * CBEV + c) * (HW * HW);
    float Ia = im[y0 * HW + x0];
    float Ib = im[y1 * HW + x0];
    float Ic = im[y0 * HW + x1];
    float Id = im[y1 * HW + x1];
    g_feats[((size_t)b * NKP + k) * CF + c] = Ia * wa + Ib * wb + Ic * wc + Id * wd;
}

// ---------------- 5) radius aggregation (ballot-broadcast) ------------------
__global__ void agg_raw_kernel(float r2) {
    int b = blockIdx.y;
    int warp = threadIdx.x >> 5, lane = threadIdx.x & 31;
    int k = blockIdx.x * 8 + warp;
    float kx = g_kpx[b][k], ky = g_kpy[b][k], kz = g_kpz[b][k];
    float acc = 0.0f;
    int cnt = 0;
    __shared__ float sx[256], sy[256], sz[256];
    for (int base = 0; base < NPTS; base += 256) {
        __syncthreads();
        int i = base + threadIdx.x;
        sx[threadIdx.x] = g_px[b][i];
        sy[threadIdx.x] = g_py[b][i];
        sz[threadIdx.x] = g_pz[b][i];
        __syncthreads();
        #pragma unroll
        for (int s = 0; s < 8; ++s) {
            int j = s * 32 + lane;
            float dx = sx[j] - kx, dy = sy[j] - ky, dz = sz[j] - kz;
            float d2 = dx * dx + dy * dy + dz * dz;
            unsigned m = __ballot_sync(0xffffffffu, d2 < r2);
            while (m) {
                int src = __ffs(m) - 1;
                m &= m - 1;
                int gp = base + s * 32 + src;
                acc += g_fraw[((size_t)b * NPTS + gp) * CRAW + lane];
                cnt++;
            }
        }
    }
    float c = fmaxf((float)cnt, 1.0f);
    g_feats[((size_t)b * NKP + k) * CF + CBEV + lane] = acc / c;
}

__global__ void agg_c3_kernel(float r2) {
    int b = blockIdx.y;
    int warp = threadIdx.x >> 5, lane = threadIdx.x & 31;
    int k = blockIdx.x * 8 + warp;
    float kx = g_kpx[b][k], ky = g_kpy[b][k], kz = g_kpz[b][k];
    float acc0 = 0.0f, acc1 = 0.0f;
    int cnt = 0;
    __shared__ float sx[256], sy[256], sz[256];
    for (int base = 0; base < MC3; base += 256) {
        __syncthreads();
        int i = base + threadIdx.x;
        sx[threadIdx.x] = g_cx[b][i];
        sy[threadIdx.x] = g_cy[b][i];
        sz[threadIdx.x] = g_cz[b][i];
        __syncthreads();
        #pragma unroll
        for (int s = 0; s < 8; ++s) {
            int j = s * 32 + lane;
            float dx = sx[j] - kx, dy = sy[j] - ky, dz = sz[j] - kz;
            float d2 = dx * dx + dy * dy + dz * dz;
            unsigned m = __ballot_sync(0xffffffffu, d2 < r2);
            while (m) {
                int src = __ffs(m) - 1;
                m &= m - 1;
                int gp = base + s * 32 + src;
                const float* fp = g_fc3 + ((size_t)b * MC3 + gp) * CC3;
                acc0 += fp[lane];
                acc1 += fp[lane + 32];
                cnt++;
            }
        }
    }
    float c = fmaxf((float)cnt, 1.0f);
    float* o = g_feats + ((size_t)b * NKP + k) * CF + CBEV + CRAW;
    o[lane] = acc0 / c;
    o[lane + 32] = acc1 / c;
}

// ---------------- 6) fuse GEMM + BN + ReLU ----------------------------------
#define ROWS_PB 16
__global__ void fuse_kernel(const float* __restrict__ W,
                            const float* __restrict__ gamma,
                            const float* __restrict__ beta,
                            const float* __restrict__ mean,
                            const float* __restrict__ var,
                            float* __restrict__ out) {
    __shared__ float sf[ROWS_PB][CF];
    int row0 = blockIdx.x * ROWS_PB;
    int tid = threadIdx.x;
    for (int idx = tid; idx < ROWS_PB * CF; idx += 128) {
        ((float*)sf)[idx] = g_feats[(size_t)row0 * CF + idx];
    }
    __syncthreads();
    int c = tid;
    float acc[ROWS_PB];
    #pragma unroll
    for (int r = 0; r < ROWS_PB; ++r) acc[r] = 0.0f;
    for (int k = 0; k < CF; ++k) {
        float w = W[k * COUT + c];
        #pragma unroll
        for (int r = 0; r < ROWS_PB; ++r) acc[r] += sf[r][k] * w;
    }
    float mu = mean[c];
    float iv = rsqrtf(var[c] + 1e-5f);
    float g = gamma[c], be = beta[c];
    #pragma unroll
    for (int r = 0; r < ROWS_PB; ++r) {
        float v = (acc[r] - mu) * iv * g + be;
        out[(size_t)(row0 + r) * COUT + c] = fmaxf(v, 0.0f);
    }
}

// ---------------- 7) keypoints output ---------------------------------------
__global__ void kpout_kernel(float* __restrict__ out) {
    int tid = blockIdx.x * blockDim.x + threadIdx.x;
    if (tid >= NB * NKP * 3) return;
    int b = tid / (NKP * 3);
    int rem = tid % (NKP * 3);
    int k = rem / 3, d = rem % 3;
    float v = (d == 0) ? g_kpx[b][k] : (d == 1 ? g_kpy[b][k] : g_kpz[b][k]);
    out[(size_t)NB * NKP * COUT + tid] = v;
}

// ---------------- launcher ---------------------------------------------------
extern "C" void kernel_launch(void* const* d_in, const int* in_sizes, int n_in,
                              void* d_out, int out_size) {
    const float* points  = (const float*)d_in[0];
    const float* bboxes  = (const float*)d_in[1];
    const float* spatial = (const float*)d_in[2];
    const float* conv3   = (const float*)d_in[3];
    const float* W_raw   = (const float*)d_in[4];
    const float* b_raw   = (const float*)d_in[5];
    const float* W_c3    = (const float*)d_in[6];
    const float* b_c3    = (const float*)d_in[7];
    const float* W_fuse  = (const float*)d_in[8];
    const float* bn_g    = (const float*)d_in[9];
    const float* bn_b    = (const float*)d_in[10];
    const float* bn_m    = (const float*)d_in[11];
    const float* bn_v    = (const float*)d_in[12];
    float* out = (float*)d_out;

    const int fps_smem = 3 * 8192 * (int)sizeof(float2);   // 196608 B
    cudaFuncSetAttribute(fps_kernel, cudaFuncAttributeMaxDynamicSharedMemorySize,
                         fps_smem);

    prep_points_kernel<<<(NB * NPTS + 255) / 256, 256>>>(points, bboxes);
    prep_c3_kernel<<<(NB * MC3 + 255) / 256, 256>>>(conv3);
    fraw_kernel<<<(NB * NPTS * CRAW + 255) / 256, 256>>>(points, W_raw, b_raw);
    fc3_kernel<<<(NB * MC3 * CC3 + 255) / 256, 256>>>(conv3, W_c3, b_c3);
    fps_kernel<<<NB, 512, fps_smem>>>();
    bev_kernel<<<dim3(NKP, NB), CBEV>>>(spatial);
    agg_raw_kernel<<<dim3(NKP / 8, NB), 256>>>(0.8f * 0.8f);
    agg_c3_kernel<<<dim3(NKP / 8, NB), 256>>>(1.6f * 1.6f);
    fuse_kernel<<<(NB * NKP) / ROWS_PB, COUT>>>(W_fuse, bn_g, bn_b, bn_m, bn_v, out);
    kpout_kernel<<<(NB * NKP * 3 + 255) / 256, 256>>>(out);
}

// round 4
// speedup vs baseline: 2.3784x; 1.1995x over previous
#include <cuda_runtime.h>
#include <cstdint>

#define NB    2
#define NPTS  16384
#define MC3   8192
#define NROI  128
#define NKP   2048
#define CBEV  256
#define CRAW  32
#define CC3   64
#define CF    (CBEV + CRAW + CC3)   // 352
#define COUT  128
#define HW    188
#define GRIDC 24
#define NCELL (GRIDC * GRIDC)       // 576
#define NCHK  512
#define FULLM 0xffffffffu

// monotonic float <-> uint key (total order; umax/umin on key == fmax/fmin)
__device__ __forceinline__ unsigned fkey(float f) {
    unsigned b = __float_as_uint(f);
    return b ^ ((unsigned)((int)b >> 31) | 0x80000000u);
}
__device__ __forceinline__ float keyf(unsigned k) {
    unsigned b = (k & 0x80000000u) ? (k ^ 0x80000000u) : ~k;
    return __uint_as_float(b);
}

// ---------------- scratch (device globals; no allocation allowed) -----------
__device__ float g_px[NB][NPTS], g_py[NB][NPTS], g_pz[NB][NPTS];
__device__ unsigned char g_valid[NB][NPTS];
__device__ unsigned short g_cell[NB][NPTS];
__device__ int g_cellstart[NB][NCELL], g_cellcur[NB][NCELL];
__device__ int g_nvalid[NB];
__device__ float g_sx[NB][NPTS], g_sy[NB][NPTS], g_sz[NB][NPTS];
__device__ unsigned short g_perm[NB][NPTS];
__device__ float4 g_meta[NB][NCHK];
__device__ float g_cx[NB][MC3], g_cy[NB][MC3], g_cz[NB][MC3];
__device__ float g_kpx[NB][NKP], g_kpy[NB][NKP], g_kpz[NB][NKP];
__device__ float g_fraw[NB * NPTS * CRAW];
__device__ float g_fc3[NB * MC3 * CC3];
__device__ float g_feats[NB * NKP * CF];

// ---------------- 1) SoA copy + ROI validity + cell id ----------------------
__global__ void prep_points_kernel(const float* __restrict__ points,
                                   const float* __restrict__ bboxes) {
    int tid = blockIdx.x * blockDim.x + threadIdx.x;
    if (tid >= NB * NPTS) return;
    int b = tid / NPTS, i = tid % NPTS;
    const float* p = points + (size_t)tid * 5;
    float x = p[0], y = p[1], z = p[2];
    g_px[b][i] = x; g_py[b][i] = y; g_pz[b][i] = z;

    float best = 3.0e38f;
    int bidx = 0;
    const float* bb0 = bboxes + (size_t)b * NROI * 7;
    for (int r = 0; r < NROI; ++r) {
        const float* bb = bb0 + r * 7;
        float dx = x - bb[0], dy = y - bb[1], dz = z - bb[2];
        float d = __fsqrt_rn(dx * dx + dy * dy + dz * dz);
        if (d < best) { best = d; bidx = r; }
    }
    const float* bb = bb0 + bidx * 7;
    float hx = bb[3] * 0.5f, hy = bb[4] * 0.5f, hz = bb[5] * 0.5f;
    float rm = __fsqrt_rn(hx * hx + hy * hy + hz * hz);
    g_valid[b][i] = (best < rm + 2.4f) ? 1 : 0;

    const float inv = (float)GRIDC / 150.4f;
    int cx = min(GRIDC - 1, max(0, (int)((x + 75.2f) * inv)));
    int cy = min(GRIDC - 1, max(0, (int)((y + 75.2f) * inv)));
    g_cell[b][i] = (unsigned short)(cy * GRIDC + cx);
}

__global__ void prep_c3_kernel(const float* __restrict__ conv3) {
    int tid = blockIdx.x * blockDim.x + threadIdx.x;
    if (tid >= NB * MC3) return;
    int b = tid / MC3, i = tid % MC3;
    const float* p = conv3 + (size_t)tid * 67;
    g_cx[b][i] = p[0]; g_cy[b][i] = p[1]; g_cz[b][i] = p[2];
}

// ---------------- 2) cell histogram + scan (one block per batch) ------------
__global__ void histscan_kernel() {
    __shared__ int h[NCELL];
    __shared__ int sa[NCELL], sb[NCELL];
    int b = blockIdx.x, t = threadIdx.x;   // 576 threads
    h[t] = 0;
    __syncthreads();
    for (int i = t; i < NPTS; i += NCELL)
        if (g_valid[b][i]) atomicAdd(&h[g_cell[b][i]], 1);
    __syncthreads();
    sa[t] = h[t];
    __syncthreads();
    int* src = sa; int* dst = sb;
    for (int off = 1; off < NCELL; off <<= 1) {
        int v = src[t];
        if (t >= off) v += src[t - off];
        dst[t] = v;
        __syncthreads();
        int* tmp = src; src = dst; dst = tmp;
    }
    int incl = src[t];
    int start = incl - h[t];
    g_cellstart[b][t] = start;
    g_cellcur[b][t] = start;
    if (t == NCELL - 1) g_nvalid[b] = incl;
}

// ---------------- 3) scatter valid points into sorted order -----------------
__global__ void scatter_kernel() {
    int tid = blockIdx.x * blockDim.x + threadIdx.x;
    if (tid >= NB * NPTS) return;
    int b = tid / NPTS, i = tid % NPTS;
    if (!g_valid[b][i]) return;
    int cell = g_cell[b][i];
    int pos = atomicAdd(&g_cellcur[b][cell], 1);
    g_sx[b][pos] = g_px[b][i];
    g_sy[b][pos] = g_py[b][i];
    g_sz[b][pos] = g_pz[b][i];
    g_perm[b][pos] = (unsigned short)i;
}

// ---------------- 4) per-chunk bounding spheres (warp per chunk) ------------
__global__ void bounds_kernel() {
    int b = blockIdx.y;
    int w = threadIdx.x >> 5, j = threadIdx.x & 31;
    int c = blockIdx.x * 8 + w;          // 64 blocks * 8 warps = 512 chunks
    int n = g_nvalid[b];
    int sz = min(32, n - 32 * c);
    float4 out;
    if (sz <= 0) {
        out = make_float4(1.0e8f, 1.0e8f, 1.0e8f, 0.0f);
    } else {
        bool in = (j < sz);
        int pos = 32 * c + j;
        float x = in ? g_sx[b][pos] : 0.0f;
        float y = in ? g_sy[b][pos] : 0.0f;
        float z = in ? g_sz[b][pos] : 0.0f;
        float xn = keyf(__reduce_min_sync(FULLM, fkey(in ? x : 3.0e38f)));
        float xm = keyf(__reduce_max_sync(FULLM, fkey(in ? x : -3.0e38f)));
        float yn = keyf(__reduce_min_sync(FULLM, fkey(in ? y : 3.0e38f)));
        float ym = keyf(__reduce_max_sync(FULLM, fkey(in ? y : -3.0e38f)));
        float zn = keyf(__reduce_min_sync(FULLM, fkey(in ? z : 3.0e38f)));
        float zm = keyf(__reduce_max_sync(FULLM, fkey(in ? z : -3.0e38f)));
        float ccx = (xn + xm) * 0.5f, ccy = (yn + ym) * 0.5f, ccz = (zn + zm) * 0.5f;
        float dx = x - ccx, dy = y - ccy, dz = z - ccz;
        float d2 = in ? (dx * dx + dy * dy + dz * dz) : -1.0f;
        float r = __fsqrt_rn(keyf(__reduce_max_sync(FULLM, fkey(d2))));
        out = make_float4(ccx, ccy, ccz, r * 1.00002f + 1.0e-3f);
    }
    if (j == 0) g_meta[b][c] = out;
}

// ---------------- 5) per-point MLPs -----------------------------------------
__global__ void fraw_kernel(const float* __restrict__ points,
                            const float* __restrict__ W,
                            const float* __restrict__ bias) {
    int tid = blockIdx.x * blockDim.x + threadIdx.x;
    if (tid >= NB * NPTS * CRAW) return;
    int c = tid & (CRAW - 1);
    int pi = tid >> 5;
    const float* p = points + (size_t)pi * 5;
    float v = p[3] * W[c] + p[4] * W[CRAW + c] + bias[c];
    g_fraw[tid] = fmaxf(v, 0.0f);
}

__global__ void fc3_kernel(const float* __restrict__ conv3,
                           const float* __restrict__ W,
                           const float* __restrict__ bias) {
    int tid = blockIdx.x * blockDim.x + threadIdx.x;
    if (tid >= NB * MC3 * CC3) return;
    int c = tid & (CC3 - 1);
    int pi = tid >> 6;
    const float* p = conv3 + (size_t)pi * 67 + 3;
    float acc = 0.0f;
    #pragma unroll 8
    for (int k = 0; k < CC3; ++k) acc += p[k] * W[k * CC3 + c];
    g_fc3[tid] = fmaxf(acc + bias[c], 0.0f);
}

// ---------------- 6) chunked exact FPS --------------------------------------
// Warp w owns chunks {16*cl + w}; lane j owns point j of each chunk
// (pos = 32*(16*cl+w)+j, coalesced). Selection = exact float max (permutation
// invariant) + min ORIGINAL index among exact-max candidates == jnp.argmax on
// the original array. Pruning: chunk skipped iff conservative lower bound on
// any new distance exceeds the chunk's current max dd (exact no-op guarantee).
__global__ void __launch_bounds__(512, 1) fps_kernel() {
    __shared__ unsigned short s_perm[NPTS];   // 32 KB
    __shared__ float4 s_meta[NCHK];           // 8 KB
    __shared__ unsigned s_wmax[16];
    __shared__ int s_sel[2];
    __shared__ float s_kx, s_ky, s_kz;

    int b = blockIdx.x, t = threadIdx.x;
    int w = t >> 5, j = t & 31;
    int n = g_nvalid[b];
    const float* sx = g_sx[b];
    const float* sy = g_sy[b];
    const float* sz = g_sz[b];

    for (int i = t; i < NPTS; i += 512) s_perm[i] = g_perm[b][i];
    if (t < NCHK) s_meta[t] = g_meta[b][t];
    if (t == 0) { s_sel[0] = 0x7fffffff; s_sel[1] = 0x7fffffff; }

    float dd[32];
    unsigned kmax = 0;   // key of max dd over chunk (16*j + w)
    #pragma unroll
    for (int cl = 0; cl < 32; ++cl) {
        int pos = 32 * (16 * cl + w) + j;
        float v = (pos < n) ? 1.0e10f : -1.0e10f;
        dd[cl] = v;
        unsigned mk = __reduce_max_sync(FULLM, fkey(v));
        if (j == cl) kmax = mk;
    }
    __syncthreads();                 // s_meta/s_perm visible to ALL threads
    float4 mt = s_meta[16 * j + w];  // this lane's chunk bounding sphere (FIXED: after barrier)

    for (int it = 0; it < NKP; ++it) {
        // ---- A: block max over per-chunk maxes (registers -> REDUX x2) ----
        unsigned key = __reduce_max_sync(FULLM, kmax);
        if (j == 0) s_wmax[w] = key;
        if (t == 0) s_sel[(it + 1) & 1] = 0x7fffffff;
        __syncthreads();                               // bar1
        unsigned k2 = __reduce_max_sync(FULLM, s_wmax[j & 15]);
        float V = keyf(k2);

        // ---- B: candidates (min original index among dd == V) ----
        int candv = 0x7fffffff, candpos = 0;
        unsigned hit = __ballot_sync(FULLM, kmax == k2);
        while (hit) {
            int cl = __ffs(hit) - 1; hit &= hit - 1;
            if (dd[cl] == V) {
                int pos = 32 * (16 * cl + w) + j;
                int o = (int)s_perm[pos];
                if (o < candv) { candv = o; candpos = pos; }
            }
        }
        int wmin = __reduce_min_sync(FULLM, candv);
        if (j == 0 && wmin != 0x7fffffff) atomicMin(&s_sel[it & 1], wmin);
        __syncthreads();                               // bar2

        // ---- C: unique winner publishes keypoint ----
        int sel = s_sel[it & 1];
        if (candv == sel) {
            float x = __ldg(sx + candpos), y = __ldg(sy + candpos), z = __ldg(sz + candpos);
            s_kx = x; s_ky = y; s_kz = z;
            g_kpx[b][it] = x; g_kpy[b][it] = y; g_kpz[b][it] = z;
        }
        __syncthreads();                               // bar3
        if (it == NKP - 1) break;
        float kx = s_kx, ky = s_ky, kz = s_kz;

        // ---- D: pruned update ----
        float dxc = kx - mt.x, dyc = ky - mt.y, dzc = kz - mt.z;
        float dc = __fsqrt_rn(dxc * dxc + dyc * dyc + dzc * dzc);
        float lhs = dc - mt.w - 1.0e-3f;
        bool skip = (lhs > 0.0f) && (lhs * lhs * 0.99999f > keyf(kmax));
        unsigned act = __ballot_sync(FULLM, !skip);
        while (act) {
            int cl = __ffs(act) - 1; act &= act - 1;
            int pos = 32 * (16 * cl + w) + j;
            float dx = __ldg(sx + pos) - kx;
            float dy = __ldg(sy + pos) - ky;
            float dz = __ldg(sz + pos) - kz;
            float nd = fmaf(dz, dz, fmaf(dy, dy, dx * dx));
            float v = fminf(dd[cl], nd);
            dd[cl] = v;
            unsigned mk = __reduce_max_sync(FULLM, fkey(v));
            if (j == cl) kmax = mk;
        }
    }
}

// ---------------- 7) bilinear BEV sampling ----------------------------------
__global__ void bev_kernel(const float* __restrict__ sf) {
    int k = blockIdx.x, b = blockIdx.y, c = threadIdx.x;
    float kx = g_kpx[b][k], ky = g_kpy[b][k];
    float xi = __fdiv_rn(__fdiv_rn(kx - (-75.2f), 0.1f), 8.0f);
    float yi = __fdiv_rn(__fdiv_rn(ky - (-75.2f), 0.1f), 8.0f);
    int x0 = min(max((int)floorf(xi), 0), HW - 1);
    int x1 = min(x0 + 1, HW - 1);
    int y0 = min(max((int)floorf(yi), 0), HW - 1);
    int y1 = min(y0 + 1, HW - 1);
    float xf0 = (float)x0, xf1 = (float)x1, yf0 = (float)y0, yf1 = (float)y1;
    float wa = (xf1 - xi) * (yf1 - yi);
    float wb = (xf1 - xi) * (yi - yf0);
    float wc = (xi - xf0) * (yf1 - yi);
    float wd = (xi - xf0) * (yi - yf0);
    const float* im = sf + ((size_t)b * CBEV + c) * (HW * HW);
    float Ia = im[y0 * HW + x0];
    float Ib = im[y1 * HW + x0];
    float Ic = im[y0 * HW + x1];
    float Id = im[y1 * HW + x1];
    g_feats[((size_t)b * NKP + k) * CF + c] = Ia * wa + Ib * wb + Ic * wc + Id * wd;
}

// ---------------- 8) radius aggregation (ballot-broadcast) ------------------
__global__ void agg_raw_kernel(float r2) {
    int b = blockIdx.y;
    int warp = threadIdx.x >> 5, lane = threadIdx.x & 31;
    int k = blockIdx.x * 8 + warp;
    float kx = g_kpx[b][k], ky = g_kpy[b][k], kz = g_kpz[b][k];
    float acc = 0.0f;
    int cnt = 0;
    __shared__ float sx[256], sy[256], sz[256];
    for (int base = 0; base < NPTS; base += 256) {
        __syncthreads();
        int i = base + threadIdx.x;
        sx[threadIdx.x] = g_px[b][i];
        sy[threadIdx.x] = g_py[b][i];
        sz[threadIdx.x] = g_pz[b][i];
        __syncthreads();
        #pragma unroll
        for (int s = 0; s < 8; ++s) {
            int jj = s * 32 + lane;
            float dx = sx[jj] - kx, dy = sy[jj] - ky, dz = sz[jj] - kz;
            float d2 = dx * dx + dy * dy + dz * dz;
            unsigned m = __ballot_sync(FULLM, d2 < r2);
            while (m) {
                int src = __ffs(m) - 1;
                m &= m - 1;
                int gp = base + s * 32 + src;
                acc += g_fraw[((size_t)b * NPTS + gp) * CRAW + lane];
                cnt++;
            }
        }
    }
    float c = fmaxf((float)cnt, 1.0f);
    g_feats[((size_t)b * NKP + k) * CF + CBEV + lane] = acc / c;
}

__global__ void agg_c3_kernel(float r2) {
    int b = blockIdx.y;
    int warp = threadIdx.x >> 5, lane = threadIdx.x & 31;
    int k = blockIdx.x * 8 + warp;
    float kx = g_kpx[b][k], ky = g_kpy[b][k], kz = g_kpz[b][k];
    float acc0 = 0.0f, acc1 = 0.0f;
    int cnt = 0;
    __shared__ float sx[256], sy[256], sz[256];
    for (int base = 0; base < MC3; base += 256) {
        __syncthreads();
        int i = base + threadIdx.x;
        sx[threadIdx.x] = g_cx[b][i];
        sy[threadIdx.x] = g_cy[b][i];
        sz[threadIdx.x] = g_cz[b][i];
        __syncthreads();
        #pragma unroll
        for (int s = 0; s < 8; ++s) {
            int jj = s * 32 + lane;
            float dx = sx[jj] - kx, dy = sy[jj] - ky, dz = sz[jj] - kz;
            float d2 = dx * dx + dy * dy + dz * dz;
            unsigned m = __ballot_sync(FULLM, d2 < r2);
            while (m) {
                int src = __ffs(m) - 1;
                m &= m - 1;
                int gp = base + s * 32 + src;
                const float* fp = g_fc3 + ((size_t)b * MC3 + gp) * CC3;
                acc0 += fp[lane];
                acc1 += fp[lane + 32];
                cnt++;
            }
        }
    }
    float c = fmaxf((float)cnt, 1.0f);
    float* o = g_feats + ((size_t)b * NKP + k) * CF + CBEV + CRAW;
    o[lane] = acc0 / c;
    o[lane + 32] = acc1 / c;
}

// ---------------- 9) fuse GEMM + BN + ReLU ----------------------------------
#define ROWS_PB 16
__global__ void fuse_kernel(const float* __restrict__ W,
                            const float* __restrict__ gamma,
                            const float* __restrict__ beta,
                            const float* __restrict__ mean,
                            const float* __restrict__ var,
                            float* __restrict__ out) {
    __shared__ float sf[ROWS_PB][CF];
    int row0 = blockIdx.x * ROWS_PB;
    int tid = threadIdx.x;
    for (int idx = tid; idx < ROWS_PB * CF; idx += 128) {
        ((float*)sf)[idx] = g_feats[(size_t)row0 * CF + idx];
    }
    __syncthreads();
    int c = tid;
    float acc[ROWS_PB];
    #pragma unroll
    for (int r = 0; r < ROWS_PB; ++r) acc[r] = 0.0f;
    for (int k = 0; k < CF; ++k) {
        float wv = W[k * COUT + c];
        #pragma unroll
        for (int r = 0; r < ROWS_PB; ++r) acc[r] += sf[r][k] * wv;
    }
    float mu = mean[c];
    float iv = rsqrtf(var[c] + 1e-5f);
    float g = gamma[c], be = beta[c];
    #pragma unroll
    for (int r = 0; r < ROWS_PB; ++r) {
        float v = (acc[r] - mu) * iv * g + be;
        out[(size_t)(row0 + r) * COUT + c] = fmaxf(v, 0.0f);
    }
}

// ---------------- 10) keypoints output --------------------------------------
__global__ void kpout_kernel(float* __restrict__ out) {
    int tid = blockIdx.x * blockDim.x + threadIdx.x;
    if (tid >= NB * NKP * 3) return;
    int b = tid / (NKP * 3);
    int rem = tid % (NKP * 3);
    int k = rem / 3, d = rem % 3;
    float v = (d == 0) ? g_kpx[b][k] : (d == 1 ? g_kpy[b][k] : g_kpz[b][k]);
    out[(size_t)NB * NKP * COUT + tid] = v;
}

// ---------------- launcher ---------------------------------------------------
extern "C" void kernel_launch(void* const* d_in, const int* in_sizes, int n_in,
                              void* d_out, int out_size) {
    const float* points  = (const float*)d_in[0];
    const float* bboxes  = (const float*)d_in[1];
    const float* spatial = (const float*)d_in[2];
    const float* conv3   = (const float*)d_in[3];
    const float* W_raw   = (const float*)d_in[4];
    const float* b_raw   = (const float*)d_in[5];
    const float* W_c3    = (const float*)d_in[6];
    const float* b_c3    = (const float*)d_in[7];
    const float* W_fuse  = (const float*)d_in[8];
    const float* bn_g    = (const float*)d_in[9];
    const float* bn_b    = (const float*)d_in[10];
    const float* bn_m    = (const float*)d_in[11];
    const float* bn_v    = (const float*)d_in[12];
    float* out = (float*)d_out;

    prep_points_kernel<<<(NB * NPTS + 255) / 256, 256>>>(points, bboxes);
    prep_c3_kernel<<<(NB * MC3 + 255) / 256, 256>>>(conv3);
    histscan_kernel<<<NB, NCELL>>>();
    scatter_kernel<<<(NB * NPTS + 255) / 256, 256>>>();
    bounds_kernel<<<dim3(64, NB), 256>>>();
    fraw_kernel<<<(NB * NPTS * CRAW + 255) / 256, 256>>>(points, W_raw, b_raw);
    fc3_kernel<<<(NB * MC3 * CC3 + 255) / 256, 256>>>(conv3, W_c3, b_c3);
    fps_kernel<<<NB, 512>>>();
    bev_kernel<<<dim3(NKP, NB), CBEV>>>(spatial);
    agg_raw_kernel<<<dim3(NKP / 8, NB), 256>>>(0.8f * 0.8f);
    agg_c3_kernel<<<dim3(NKP / 8, NB), 256>>>(1.6f * 1.6f);
    fuse_kernel<<<(NB * NKP) / ROWS_PB, COUT>>>(W_fuse, bn_g, bn_b, bn_m, bn_v, out);
    kpout_kernel<<<(NB * NKP * 3 + 255) / 256, 256>>>(out);
}